// round 12
// baseline (speedup 1.0000x reference)
#include <cuda_runtime.h>
#include <cuda_fp16.h>
#include <cstdint>
#include <math.h>

#define EMBED 256
#define PAIRS 15
#define MROWS 16384
#define KPAIR 512
#define KFIN  3840

#define BM 64
#define KC 64
#define NTHREADS 512
#define PITCH 144                         // A/B smem row: 64 fp16 = 128B + 16B pad
#define ATILE (64 * PITCH)                // 9216 B
#define BTILE (256 * PITCH)               // 36864 B
#define BUFB  (ATILE + BTILE)             // 46080 B  [A][B]
#define HPITCH 528                        // 64-row H tile: 256 fp16 + 16B pad
#define HOFF  (3 * BUFB)                  // 138240
#define SMEM_BYTES (HOFF + 64 * HPITCH)   // 172032

#define NCH1 (KPAIR / KC)                 // 8
#define NCH2 (EMBED / KC)                 // 4

// ---- scratch (static device globals; allocation-guard-safe) ----
static __device__ __half g_Wpt[(size_t)PAIRS * EMBED * KPAIR];  // [p][n][k] fp16
static __device__ __half g_Wft[(size_t)EMBED * KFIN];           // [n][k]   fp16

__constant__ int c_pi[PAIRS] = {0,0,0,0,0,1,1,1,1,2,2,2,3,3,4};
__constant__ int c_pj[PAIRS] = {1,2,3,4,5,2,3,4,5,3,4,5,4,5,5};

__device__ __forceinline__ bool pair_on(const int* __restrict__ NAS, int p) {
    int i = c_pi[p], j = c_pj[p];
    int ni = (i < 2) ? 1 : __ldg(&NAS[i]);
    int nj = (j < 2) ? 1 : __ldg(&NAS[j]);
    return (ni != 0) && (nj != 0);
}
__device__ __forceinline__ uint32_t smem_u32(const void* p) {
    uint32_t a;
    asm("{ .reg .u64 t; cvta.to.shared.u64 t, %1; cvt.u32.u64 %0, t; }" : "=r"(a) : "l"(p));
    return a;
}

// ---- base-target PTX primitives (sm_80 baseline; valid on plain sm_103) ----
__device__ __forceinline__ void cp16(uint32_t dst, const void* src) {
    asm volatile("cp.async.cg.shared.global [%0], [%1], 16;" :: "r"(dst), "l"(src));
}
#define CP_COMMIT()      asm volatile("cp.async.commit_group;" ::: "memory")
#define CP_WAIT(n)       asm volatile("cp.async.wait_group %0;" :: "n"(n) : "memory")
#define LDM_X4(r, addr) \
    asm volatile("ldmatrix.sync.aligned.m8n8.x4.shared.b16 {%0,%1,%2,%3}, [%4];" \
        : "=r"((r)[0]), "=r"((r)[1]), "=r"((r)[2]), "=r"((r)[3]) : "r"(addr))
#define LDS32(v, addr) \
    asm volatile("ld.shared.b32 %0, [%1];" : "=r"(v) : "r"(addr))
#define MMA(d, a, b0, b1) \
    asm volatile("mma.sync.aligned.m16n8k16.row.col.f32.f16.f16.f32 " \
        "{%0,%1,%2,%3}, {%4,%5,%6,%7}, {%8,%9}, {%0,%1,%2,%3};" \
        : "+f"((d)[0]), "+f"((d)[1]), "+f"((d)[2]), "+f"((d)[3]) \
        : "r"((a)[0]), "r"((a)[1]), "r"((a)[2]), "r"((a)[3]), "r"(b0), "r"(b1))

// ---------------------------------------------------------------------------
// Prep: transpose weights to [n][k], fp16. 4 k-tiles per block.
// ---------------------------------------------------------------------------
__global__ void prep_wpair(const float* __restrict__ W_pair, const int* __restrict__ NAS) {
    int p = blockIdx.z;
    if (!pair_on(NAS, p)) return;
    __shared__ float tsh[32][33];
    int n0 = blockIdx.y * 32;
    int tx = threadIdx.x, ty = threadIdx.y;
    const float* W = W_pair + (size_t)p * KPAIR * EMBED;
    for (int kt = 0; kt < 4; kt++) {
        int k0 = blockIdx.x * 128 + kt * 32;
        #pragma unroll
        for (int i = 0; i < 4; i++)
            tsh[ty + i*8][tx] = W[(size_t)(k0 + ty + i*8) * EMBED + n0 + tx];
        __syncthreads();
        #pragma unroll
        for (int i = 0; i < 4; i++) {
            size_t o = ((size_t)p * EMBED + n0 + ty + i*8) * KPAIR + k0 + tx;
            g_Wpt[o] = __float2half_rn(tsh[tx][ty + i*8]);
        }
        __syncthreads();
    }
}

__global__ void prep_wfinal(const float* __restrict__ W_final, const int* __restrict__ NAS) {
    __shared__ float tsh[32][33];
    int n0 = blockIdx.y * 32;
    int tx = threadIdx.x, ty = threadIdx.y;
    for (int kt = 0; kt < 4; kt++) {
        int k0 = blockIdx.x * 128 + kt * 32;
        if (pair_on(NAS, k0 >> 8)) {
            #pragma unroll
            for (int i = 0; i < 4; i++)
                tsh[ty + i*8][tx] = W_final[(size_t)(k0 + ty + i*8) * EMBED + n0 + tx];
            __syncthreads();
            #pragma unroll
            for (int i = 0; i < 4; i++) {
                size_t o = (size_t)(n0 + ty + i*8) * KFIN + k0 + tx;
                g_Wft[o] = __float2half_rn(tsh[tx][ty + i*8]);
            }
        }
        __syncthreads();
    }
}

// ---------------------------------------------------------------------------
// Loaders
// ---------------------------------------------------------------------------
__device__ __forceinline__ void lda_regs(float4 r[2], const float* __restrict__ s) {
    r[0] = *reinterpret_cast<const float4*>(s);
    r[1] = *reinterpret_cast<const float4*>(s + 4);
}
// A: 64 rows x 64 k fp32 -> fp16; all 512 threads, 8 fp32 each.
__device__ __forceinline__ void sts_cvt(char* smem, int bufofs, uint32_t dofs,
                                        const float4 r[2]) {
    float f[8] = {r[0].x, r[0].y, r[0].z, r[0].w, r[1].x, r[1].y, r[1].z, r[1].w};
    unsigned short h[8];
    #pragma unroll
    for (int q = 0; q < 8; q++)
        h[q] = __half_as_ushort(__float2half_rn(f[q]));
    *reinterpret_cast<uint4*>(smem + bufofs + dofs) =
        make_uint4((uint32_t)h[0] | ((uint32_t)h[1] << 16), (uint32_t)h[2] | ((uint32_t)h[3] << 16),
                   (uint32_t)h[4] | ((uint32_t)h[5] << 16), (uint32_t)h[6] | ((uint32_t)h[7] << 16));
}
// B tile: 256 rows(n) x 64 k fp16, 2 threads/row (512 threads), 64B each.
__device__ __forceinline__ void cp_b(uint32_t buf, int tid, const __half* bsrc, size_t stride) {
    const int row = tid >> 1, h = tid & 1;
    const uint32_t d = buf + ATILE + row * PITCH + h * 64;
    const __half* s = bsrc + (size_t)row * stride + h * 32;
    cp16(d, s); cp16(d + 16, s + 8); cp16(d + 32, s + 16); cp16(d + 48, s + 24);
}

// ---------------------------------------------------------------------------
// Compute. 16 warps: warpM = wid&1 (32 rows), warpN = wid>>1 (32 cols of 256).
// ---------------------------------------------------------------------------
__device__ __forceinline__ void compute1(uint32_t buf, int warpM, int warpN,
                                         int lid, float acc[2][4][4]) {
    const int arow = lid & 15, ka = (lid >> 4) & 1;
    const int g = lid >> 2, t = lid & 3;
    const uint32_t bbase = buf + ATILE + (warpN * 32 + g) * PITCH + t * 4;
    #pragma unroll
    for (int ks = 0; ks < 4; ks++) {
        uint32_t a[2][4];
        #pragma unroll
        for (int mt = 0; mt < 2; mt++) {
            uint32_t ad = buf + (warpM*32 + mt*16 + arow) * PITCH + ks*32 + ka*16;
            LDM_X4(a[mt], ad);
        }
        #pragma unroll
        for (int nt = 0; nt < 4; nt++) {
            uint32_t bd = bbase + nt * 8 * PITCH + ks * 32;
            uint32_t b0, b1;
            LDS32(b0, bd); LDS32(b1, bd + 16);
            MMA(acc[0][nt], a[0], b0, b1);
            MMA(acc[1][nt], a[1], b0, b1);
        }
    }
}
__device__ __forceinline__ void compute2(uint32_t buf, uint32_t hbase, int c2,
                                         int warpM, int warpN, int lid, float acc[2][4][4]) {
    const int arow = lid & 15, ka = (lid >> 4) & 1;
    const int g = lid >> 2, t = lid & 3;
    const uint32_t bbase = buf + ATILE + (warpN * 32 + g) * PITCH + t * 4;
    #pragma unroll
    for (int ks = 0; ks < 4; ks++) {
        uint32_t a[2][4];
        #pragma unroll
        for (int mt = 0; mt < 2; mt++) {
            uint32_t ad = hbase + (warpM*32 + mt*16 + arow) * HPITCH
                        + c2*128 + ks*32 + ka*16;
            LDM_X4(a[mt], ad);
        }
        #pragma unroll
        for (int nt = 0; nt < 4; nt++) {
            uint32_t bd = bbase + nt * 8 * PITCH + ks * 32;
            uint32_t b0, b1;
            LDS32(b0, bd); LDS32(b1, bd + 16);
            MMA(acc[0][nt], a[0], b0, b1);
            MMA(acc[1][nt], a[1], b0, b1);
        }
    }
}

// ---------------------------------------------------------------------------
// Fused kernel: per 64-row block, loop active pairs:
//   H = tanh([Fi|Fj] @ Wp + bp) (smem) ; out_acc += H @ Wft[p]
// Cross-phase stitched cp.async pipeline (GEMM2 B prefetch during H epilogue;
// next pair's GEMM1 prologue during GEMM2 tail).
// ---------------------------------------------------------------------------
__global__ __launch_bounds__(NTHREADS, 1)
void fused_mma(const float* __restrict__ features,
               const float* __restrict__ b_pair,
               const float* __restrict__ b_final,
               const int*   __restrict__ NAS,
               float*       __restrict__ out)
{
    const int rowBase = blockIdx.x * BM;
    extern __shared__ char smem[];
    const uint32_t sb = smem_u32(smem);
    const uint32_t hbase = sb + HOFF;
    const int tid = threadIdx.x, wid = tid >> 5, lid = tid & 31;
    const int warpM = wid & 1, warpN = wid >> 1;
    const int g = lid >> 2, t = lid & 3;

    // A-loader lane mapping (512 threads; 8/row x 8 fp32)
    const int arow = tid >> 3, aq = tid & 7;
    const uint32_t adofs = arow * PITCH + aq * 16;             // smem bytes
    const size_t   arofs = (size_t)arow * EMBED + aq * 8;      // gmem elems

    int plist[PAIRS], nact = 0;
    #pragma unroll
    for (int p = 0; p < PAIRS; p++)
        if (pair_on(NAS, p)) plist[nact++] = p;

    float acc2[2][4][4];
    #pragma unroll
    for (int i = 0; i < 2; i++)
        #pragma unroll
        for (int j = 0; j < 4; j++)
            #pragma unroll
            for (int e = 0; e < 4; e++) acc2[i][j][e] = 0.0f;

    float4 rA[2];

    // ---- prologue for first pair ----
    {
        const int p = plist[0];
        const float* Fi = features + ((size_t)c_pi[p] * MROWS + rowBase) * EMBED;
        const __half* WB = g_Wpt + (size_t)p * EMBED * KPAIR;
        lda_regs(rA, Fi + arofs);
        sts_cvt(smem, 0, adofs, rA);
        cp_b(sb, tid, WB, KPAIR); CP_COMMIT();
        lda_regs(rA, Fi + arofs + KC);
        cp_b(sb + BUFB, tid, WB + KC, KPAIR); CP_COMMIT();
    }

    for (int pi = 0; pi < nact; pi++) {
        const int p = plist[pi];
        const float* Fi = features + ((size_t)c_pi[p] * MROWS + rowBase) * EMBED;
        const float* Fj = features + ((size_t)c_pj[p] * MROWS + rowBase) * EMBED;
        const __half* WB = g_Wpt + (size_t)p * EMBED * KPAIR;
        const __half* WF = g_Wft + (size_t)p * EMBED;

        float acc1[2][4][4];
        #pragma unroll
        for (int i = 0; i < 2; i++)
            #pragma unroll
            for (int j = 0; j < 4; j++)
                #pragma unroll
                for (int e = 0; e < 4; e++) acc1[i][j][e] = 0.0f;

        // ---- GEMM1: 8 chunks over K=512 ----
        for (int c = 0; c < NCH1; c++) {
            if (c + 1 < NCH1) sts_cvt(smem, ((c + 1) % 3) * BUFB, adofs, rA);
            if (c + 2 < NCH1) {
                const int k0 = (c + 2) * KC;
                const float* base = (k0 < EMBED) ? Fi : Fj;
                lda_regs(rA, base + arofs + (k0 & (EMBED - 1)));
            }
            if (c + 1 < NCH1) { CP_WAIT(1); } else { CP_WAIT(0); }
            __syncthreads();
            if (c + 2 < NCH1) {
                cp_b(sb + ((c + 2) % 3) * BUFB, tid, WB + (c + 2) * KC, KPAIR);
                CP_COMMIT();
            }
            compute1(sb + (c % 3) * BUFB, warpM, warpN, lid, acc1);
        }

        // prefetch GEMM2 chunks 0,1 (bufs (8+0)%3=2, (8+1)%3=0) — fly during epilogue
        cp_b(sb + 2 * BUFB, tid, WF, KFIN); CP_COMMIT();
        cp_b(sb,            tid, WF + KC, KFIN); CP_COMMIT();

        // ---- H epilogue: bias + tanh -> fp16 into smem H ----
        #pragma unroll
        for (int mt = 0; mt < 2; mt++) {
            const int r0 = warpM * 32 + mt * 16 + g;
            char* hrow0 = smem + HOFF + (size_t)r0 * HPITCH;
            char* hrow1 = hrow0 + 8 * HPITCH;
            #pragma unroll
            for (int nt = 0; nt < 4; nt++) {
                const int colP = warpN * 32 + nt * 8 + 2 * t;
                const float b0 = __ldg(&b_pair[p * EMBED + colP]);
                const float b1 = __ldg(&b_pair[p * EMBED + colP + 1]);
                *reinterpret_cast<__half2*>(hrow0 + colP * 2) =
                    __floats2half2_rn(tanhf(acc1[mt][nt][0] + b0), tanhf(acc1[mt][nt][1] + b1));
                *reinterpret_cast<__half2*>(hrow1 + colP * 2) =
                    __floats2half2_rn(tanhf(acc1[mt][nt][2] + b0), tanhf(acc1[mt][nt][3] + b1));
            }
        }
        __syncthreads();   // H visible; GEMM1 buffers no longer read

        // ---- GEMM2: 4 chunks over this pair's 256-wide K segment ----
        for (int c = 0; c < NCH2; c++) {
            if (c + 1 < NCH2) { CP_WAIT(1); } else { CP_WAIT(0); }
            __syncthreads();
            if (c + 2 < NCH2) {
                cp_b(sb + ((NCH1 + c + 2) % 3) * BUFB, tid, WF + (c + 2) * KC, KFIN);
                CP_COMMIT();
            }
            if (c == NCH2 - 1 && pi + 1 < nact) {
                // next pair's GEMM1 prologue, overlapped with last GEMM2 compute
                const int np = plist[pi + 1];
                const float* nFi = features + ((size_t)c_pi[np] * MROWS + rowBase) * EMBED;
                const __half* nWB = g_Wpt + (size_t)np * EMBED * KPAIR;
                lda_regs(rA, nFi + arofs);
                sts_cvt(smem, 0, adofs, rA);
                cp_b(sb, tid, nWB, KPAIR); CP_COMMIT();
                lda_regs(rA, nFi + arofs + KC);
                cp_b(sb + BUFB, tid, nWB + KC, KPAIR); CP_COMMIT();
            }
            compute2(sb + ((NCH1 + c) % 3) * BUFB, hbase, c, warpM, warpN, lid, acc2);
        }
        __syncthreads();   // GEMM2 reads done before next pair overwrites buffers
    }

    // ---- final epilogue: + b_final, fp32 out ----
    #pragma unroll
    for (int mt = 0; mt < 2; mt++) {
        const int r0 = rowBase + warpM * 32 + mt * 16 + g;
        #pragma unroll
        for (int nt = 0; nt < 4; nt++) {
            const int colG = warpN * 32 + nt * 8 + 2 * t;
            const float b0 = __ldg(&b_final[colG]);
            const float b1 = __ldg(&b_final[colG + 1]);
            float2 v0 = make_float2(acc2[mt][nt][0] + b0, acc2[mt][nt][1] + b1);
            float2 v1 = make_float2(acc2[mt][nt][2] + b0, acc2[mt][nt][3] + b1);
            *reinterpret_cast<float2*>(out + (size_t)r0 * EMBED + colG)       = v0;
            *reinterpret_cast<float2*>(out + (size_t)(r0 + 8) * EMBED + colG) = v1;
        }
    }
}

extern "C" void kernel_launch(void* const* d_in, const int* in_sizes, int n_in,
                              void* d_out, int out_size)
{
    const float* features = (const float*)d_in[0];
    const float* W_pair   = (const float*)d_in[1];
    const float* b_pair   = (const float*)d_in[2];
    const float* W_final  = (const float*)d_in[3];
    const float* b_final  = (const float*)d_in[4];
    const int*   NAS      = (const int*)d_in[5];
    float* out = (float*)d_out;

    cudaFuncSetAttribute(fused_mma, cudaFuncAttributeMaxDynamicSharedMemorySize, SMEM_BYTES);

    prep_wpair <<<dim3(KPAIR/128, EMBED/32, PAIRS), dim3(32, 8)>>>(W_pair, NAS);
    prep_wfinal<<<dim3(KFIN/128,  EMBED/32),        dim3(32, 8)>>>(W_final, NAS);

    fused_mma<<<dim3(MROWS/BM), NTHREADS, SMEM_BYTES>>>(features, b_pair, b_final, NAS, out);
}

// round 13
// speedup vs baseline: 1.1711x; 1.1711x over previous
#include <cuda_runtime.h>
#include <cuda_fp16.h>
#include <cstdint>
#include <math.h>

#define EMBED 256
#define PAIRS 15
#define MROWS 16384
#define KPAIR 512
#define KFIN  3840

#define BM 64
#define KC 32
#define NTHREADS 512
#define PITCH 80                          // A smem row: 32 fp16 = 64B + 16B pad
#define ATILE (64 * PITCH)                // 5120 B
#define PITCHB 528                        // B smem row: 256 fp16 = 512B + 16B pad
#define BTILE (KC * PITCHB)               // 16896 B   [k][n] natural layout
#define BUFB  (ATILE + BTILE)             // 22016 B
#define HPITCH 528
#define HOFF  (3 * BUFB)                  // 66048
#define SMEM_BYTES (HOFF + 64 * HPITCH)   // 99840

#define NCH1 (KPAIR / KC)                 // 16
#define NCH2 (EMBED / KC)                 // 8

// ---- fp16 weights, original [k][n] layouts (allocation-guard-safe) ----
static __device__ __half g_Wp16[(size_t)PAIRS * KPAIR * EMBED];  // [p][k][n]
static __device__ __half g_Wf16[(size_t)KFIN * EMBED];           // [k][n]

__constant__ int c_pi[PAIRS] = {0,0,0,0,0,1,1,1,1,2,2,2,3,3,4};
__constant__ int c_pj[PAIRS] = {1,2,3,4,5,2,3,4,5,3,4,5,4,5,5};

__device__ __forceinline__ bool pair_on(const int* __restrict__ NAS, int p) {
    int i = c_pi[p], j = c_pj[p];
    int ni = (i < 2) ? 1 : __ldg(&NAS[i]);
    int nj = (j < 2) ? 1 : __ldg(&NAS[j]);
    return (ni != 0) && (nj != 0);
}
__device__ __forceinline__ uint32_t smem_u32(const void* p) {
    uint32_t a;
    asm("{ .reg .u64 t; cvta.to.shared.u64 t, %1; cvt.u32.u64 %0, t; }" : "=r"(a) : "l"(p));
    return a;
}

// ---- base-target PTX primitives (sm_80 baseline; valid on plain sm_103) ----
__device__ __forceinline__ void cp16(uint32_t dst, const void* src) {
    asm volatile("cp.async.cg.shared.global [%0], [%1], 16;" :: "r"(dst), "l"(src));
}
#define CP_COMMIT()      asm volatile("cp.async.commit_group;" ::: "memory")
#define CP_WAIT(n)       asm volatile("cp.async.wait_group %0;" :: "n"(n) : "memory")
#define LDM_X4(r, addr) \
    asm volatile("ldmatrix.sync.aligned.m8n8.x4.shared.b16 {%0,%1,%2,%3}, [%4];" \
        : "=r"((r)[0]), "=r"((r)[1]), "=r"((r)[2]), "=r"((r)[3]) : "r"(addr))
#define LDM_X4T(r, addr) \
    asm volatile("ldmatrix.sync.aligned.m8n8.x4.trans.shared.b16 {%0,%1,%2,%3}, [%4];" \
        : "=r"((r)[0]), "=r"((r)[1]), "=r"((r)[2]), "=r"((r)[3]) : "r"(addr))
#define MMA(d, a, b0, b1) \
    asm volatile("mma.sync.aligned.m16n8k16.row.col.f32.f16.f16.f32 " \
        "{%0,%1,%2,%3}, {%4,%5,%6,%7}, {%8,%9}, {%0,%1,%2,%3};" \
        : "+f"((d)[0]), "+f"((d)[1]), "+f"((d)[2]), "+f"((d)[3]) \
        : "r"((a)[0]), "r"((a)[1]), "r"((a)[2]), "r"((a)[3]), "r"(b0), "r"(b1))

// ---------------------------------------------------------------------------
// Prep: single elementwise fp32 -> fp16 convert for both weight tensors.
// ---------------------------------------------------------------------------
#define NP1 ((size_t)PAIRS * KPAIR * EMBED)   // 1966080
#define NP2 ((size_t)KFIN * EMBED)            //  983040
__global__ void prep_convert(const float* __restrict__ W_pair,
                             const float* __restrict__ W_final) {
    size_t i = ((size_t)blockIdx.x * blockDim.x + threadIdx.x) * 4;
    const float* src; __half* dst; size_t o;
    if (i < NP1) { src = W_pair;  dst = g_Wp16; o = i; }
    else         { src = W_final; dst = g_Wf16; o = i - NP1; }
    float4 v = *reinterpret_cast<const float4*>(src + o);
    __half2 h0 = __floats2half2_rn(v.x, v.y);
    __half2 h1 = __floats2half2_rn(v.z, v.w);
    *reinterpret_cast<__half2*>(dst + o)     = h0;
    *reinterpret_cast<__half2*>(dst + o + 2) = h1;
}

// ---------------------------------------------------------------------------
// Loaders
// ---------------------------------------------------------------------------
__device__ __forceinline__ void lda_regs(float4 r[2], const float* __restrict__ s) {
    r[0] = *reinterpret_cast<const float4*>(s);
    r[1] = *reinterpret_cast<const float4*>(s + 4);
}
// A: 64 rows x 32 k fp32 -> fp16; threads 0..255 (4/row x 8 fp32).
__device__ __forceinline__ void sts_cvt(char* smem, int bufofs, uint32_t dofs,
                                        const float4 r[2]) {
    float f[8] = {r[0].x, r[0].y, r[0].z, r[0].w, r[1].x, r[1].y, r[1].z, r[1].w};
    unsigned short h[8];
    #pragma unroll
    for (int q = 0; q < 8; q++)
        h[q] = __half_as_ushort(__float2half_rn(f[q]));
    *reinterpret_cast<uint4*>(smem + bufofs + dofs) =
        make_uint4((uint32_t)h[0] | ((uint32_t)h[1] << 16), (uint32_t)h[2] | ((uint32_t)h[3] << 16),
                   (uint32_t)h[4] | ((uint32_t)h[5] << 16), (uint32_t)h[6] | ((uint32_t)h[7] << 16));
}
// B tile: [32 k][256 n] fp16, contiguous 512B rows; 16 threads/row x 32B.
__device__ __forceinline__ void cp_bk(uint32_t buf, int tid, const __half* bsrc) {
    const int row = tid >> 4, c = tid & 15;
    const uint32_t d = buf + ATILE + row * PITCHB + c * 32;
    const __half* s = bsrc + (size_t)row * EMBED + c * 16;
    cp16(d, s); cp16(d + 16, s + 8);
}

// ---------------------------------------------------------------------------
// Compute. 16 warps: warpM = wid&1 (32 rows), warpN = wid>>1 (32 of 256 cols).
// B fragments via ldmatrix.x4.trans on [k][n] smem.
// ---------------------------------------------------------------------------
__device__ __forceinline__ void compute1(uint32_t buf, uint32_t laneB, int warpM, int warpN,
                                         int lid, float acc[2][4][4]) {
    const int arow = lid & 15, ka = (lid >> 4) & 1;
    const uint32_t bB = buf + ATILE + warpN * 64 + laneB;
    #pragma unroll
    for (int ks = 0; ks < 2; ks++) {
        uint32_t a[2][4];
        #pragma unroll
        for (int mt = 0; mt < 2; mt++) {
            uint32_t ad = buf + (warpM*32 + mt*16 + arow) * PITCH + ks*32 + ka*16;
            LDM_X4(a[mt], ad);
        }
        #pragma unroll
        for (int ntp = 0; ntp < 2; ntp++) {
            uint32_t b[4];
            LDM_X4T(b, bB + ks * 16 * PITCHB + ntp * 32);
            MMA(acc[0][2*ntp],   a[0], b[0], b[1]);
            MMA(acc[1][2*ntp],   a[1], b[0], b[1]);
            MMA(acc[0][2*ntp+1], a[0], b[2], b[3]);
            MMA(acc[1][2*ntp+1], a[1], b[2], b[3]);
        }
    }
}
__device__ __forceinline__ void compute2(uint32_t buf, uint32_t laneB, uint32_t hbase, int c2,
                                         int warpM, int warpN, int lid, float acc[2][4][4]) {
    const int arow = lid & 15, ka = (lid >> 4) & 1;
    const uint32_t bB = buf + ATILE + warpN * 64 + laneB;
    #pragma unroll
    for (int ks = 0; ks < 2; ks++) {
        uint32_t a[2][4];
        #pragma unroll
        for (int mt = 0; mt < 2; mt++) {
            uint32_t ad = hbase + (warpM*32 + mt*16 + arow) * HPITCH
                        + c2*64 + ks*32 + ka*16;
            LDM_X4(a[mt], ad);
        }
        #pragma unroll
        for (int ntp = 0; ntp < 2; ntp++) {
            uint32_t b[4];
            LDM_X4T(b, bB + ks * 16 * PITCHB + ntp * 32);
            MMA(acc[0][2*ntp],   a[0], b[0], b[1]);
            MMA(acc[1][2*ntp],   a[1], b[0], b[1]);
            MMA(acc[0][2*ntp+1], a[0], b[2], b[3]);
            MMA(acc[1][2*ntp+1], a[1], b[2], b[3]);
        }
    }
}

// ---------------------------------------------------------------------------
// Fused kernel: per 64-row block, loop active pairs:
//   H = tanh([Fi|Fj] @ Wp + bp) (smem) ; out_acc += H @ Wft[p]
// ---------------------------------------------------------------------------
__global__ __launch_bounds__(NTHREADS, 1)
void fused_mma(const float* __restrict__ features,
               const float* __restrict__ b_pair,
               const float* __restrict__ b_final,
               const int*   __restrict__ NAS,
               float*       __restrict__ out)
{
    const int rowBase = blockIdx.x * BM;
    extern __shared__ char smem[];
    const uint32_t sb = smem_u32(smem);
    const uint32_t hbase = sb + HOFF;
    const int tid = threadIdx.x, wid = tid >> 5, lid = tid & 31;
    const int warpM = wid & 1, warpN = wid >> 1;
    const int g = lid >> 2, t = lid & 3;
    const bool aldr = (tid < 256);

    // ldmatrix.trans lane address offset within warp's B block:
    // matrix m = lid>>3 (0..3), row r = lid&7; k-part (m&1)*8 + r; n-part (m>>1)*8
    const uint32_t laneB = (uint32_t)(((lid & 7) + ((lid >> 3) & 1) * 8) * PITCHB
                                      + ((lid >> 4) * 8) * 2);

    // A-loader lane mapping (threads 0..255; 4/row x 8 fp32)
    const int arow = tid & 63, aq = (tid >> 6) & 3;
    const uint32_t adofs = arow * PITCH + aq * 16;
    const size_t   arofs = (size_t)arow * EMBED + aq * 8;

    int plist[PAIRS], nact = 0;
    #pragma unroll
    for (int p = 0; p < PAIRS; p++)
        if (pair_on(NAS, p)) plist[nact++] = p;

    float acc2[2][4][4];
    #pragma unroll
    for (int i = 0; i < 2; i++)
        #pragma unroll
        for (int j = 0; j < 4; j++)
            #pragma unroll
            for (int e = 0; e < 4; e++) acc2[i][j][e] = 0.0f;

    for (int pi = 0; pi < nact; pi++) {
        const int p = plist[pi];
        const float* Fi = features + ((size_t)c_pi[p] * MROWS + rowBase) * EMBED;
        const float* Fj = features + ((size_t)c_pj[p] * MROWS + rowBase) * EMBED;
        const __half* WB = g_Wp16 + (size_t)p * KPAIR * EMBED;   // [k][n]

        float acc1[2][4][4];
        #pragma unroll
        for (int i = 0; i < 2; i++)
            #pragma unroll
            for (int j = 0; j < 4; j++)
                #pragma unroll
                for (int e = 0; e < 4; e++) acc1[i][j][e] = 0.0f;

        // ---- GEMM1: 16 chunks over K=512, triple-buffered ----
        float4 rA[2];
        if (aldr) {
            lda_regs(rA, Fi + arofs);
            sts_cvt(smem, 0, adofs, rA);
        }
        cp_bk(sb, tid, WB); CP_COMMIT();
        if (aldr) lda_regs(rA, Fi + arofs + KC);
        cp_bk(sb + BUFB, tid, WB + (size_t)KC * EMBED); CP_COMMIT();

        for (int c = 0; c < NCH1; c++) {
            if (aldr) {
                if (c + 1 < NCH1) sts_cvt(smem, ((c + 1) % 3) * BUFB, adofs, rA);
                if (c + 2 < NCH1) {
                    const int k0 = (c + 2) * KC;
                    const float* base = (k0 < EMBED) ? Fi : Fj;
                    lda_regs(rA, base + arofs + (k0 & (EMBED - 1)));
                }
            }
            if (c + 1 < NCH1) { CP_WAIT(1); } else { CP_WAIT(0); }
            __syncthreads();
            if (c + 2 < NCH1) {
                cp_bk(sb + ((c + 2) % 3) * BUFB, tid, WB + (size_t)(c + 2) * KC * EMBED);
                CP_COMMIT();
            }
            compute1(sb + (c % 3) * BUFB, laneB, warpM, warpN, lid, acc1);
        }

        // ---- H epilogue: bias + tanh -> fp16 into smem H ----
        #pragma unroll
        for (int mt = 0; mt < 2; mt++) {
            const int r0 = warpM * 32 + mt * 16 + g;
            char* hrow0 = smem + HOFF + (size_t)r0 * HPITCH;
            char* hrow1 = hrow0 + 8 * HPITCH;
            #pragma unroll
            for (int nt = 0; nt < 4; nt++) {
                const int colP = warpN * 32 + nt * 8 + 2 * t;
                const float b0 = __ldg(&b_pair[p * EMBED + colP]);
                const float b1 = __ldg(&b_pair[p * EMBED + colP + 1]);
                *reinterpret_cast<__half2*>(hrow0 + colP * 2) =
                    __floats2half2_rn(tanhf(acc1[mt][nt][0] + b0), tanhf(acc1[mt][nt][1] + b1));
                *reinterpret_cast<__half2*>(hrow1 + colP * 2) =
                    __floats2half2_rn(tanhf(acc1[mt][nt][2] + b0), tanhf(acc1[mt][nt][3] + b1));
            }
        }
        __syncthreads();   // H visible; GEMM1 buffers no longer read

        // ---- GEMM2: 8 chunks over this pair's 256-wide K segment ----
        const __half* WF = g_Wf16 + (size_t)p * EMBED * EMBED;   // rows k=p*256..
        cp_bk(sb, tid, WF); CP_COMMIT();
        cp_bk(sb + BUFB, tid, WF + (size_t)KC * EMBED); CP_COMMIT();
        for (int c = 0; c < NCH2; c++) {
            if (c + 1 < NCH2) { CP_WAIT(1); } else { CP_WAIT(0); }
            __syncthreads();
            if (c + 2 < NCH2) {
                cp_bk(sb + ((c + 2) % 3) * BUFB, tid, WF + (size_t)(c + 2) * KC * EMBED);
                CP_COMMIT();
            }
            compute2(sb + (c % 3) * BUFB, laneB, hbase, c, warpM, warpN, lid, acc2);
        }
        __syncthreads();   // buffers/H free before next pair
    }

    // ---- final epilogue: + b_final, fp32 out ----
    #pragma unroll
    for (int mt = 0; mt < 2; mt++) {
        const int r0 = rowBase + warpM * 32 + mt * 16 + g;
        #pragma unroll
        for (int nt = 0; nt < 4; nt++) {
            const int colG = warpN * 32 + nt * 8 + 2 * t;
            const float b0 = __ldg(&b_final[colG]);
            const float b1 = __ldg(&b_final[colG + 1]);
            float2 v0 = make_float2(acc2[mt][nt][0] + b0, acc2[mt][nt][1] + b1);
            float2 v1 = make_float2(acc2[mt][nt][2] + b0, acc2[mt][nt][3] + b1);
            *reinterpret_cast<float2*>(out + (size_t)r0 * EMBED + colG)       = v0;
            *reinterpret_cast<float2*>(out + (size_t)(r0 + 8) * EMBED + colG) = v1;
        }
    }
}

extern "C" void kernel_launch(void* const* d_in, const int* in_sizes, int n_in,
                              void* d_out, int out_size)
{
    const float* features = (const float*)d_in[0];
    const float* W_pair   = (const float*)d_in[1];
    const float* b_pair   = (const float*)d_in[2];
    const float* W_final  = (const float*)d_in[3];
    const float* b_final  = (const float*)d_in[4];
    const int*   NAS      = (const int*)d_in[5];
    float* out = (float*)d_out;

    cudaFuncSetAttribute(fused_mma, cudaFuncAttributeMaxDynamicSharedMemorySize, SMEM_BYTES);

    const int nvec = (int)((NP1 + NP2) / 4);                 // 737280 float4s
    prep_convert<<<nvec / 256, 256>>>(W_pair, W_final);

    fused_mma<<<dim3(MROWS/BM), NTHREADS, SMEM_BYTES>>>(features, b_pair, b_final, NAS, out);
}

// round 14
// speedup vs baseline: 1.2152x; 1.0377x over previous
#include <cuda_runtime.h>
#include <cuda_fp16.h>
#include <cstdint>
#include <math.h>

#define EMBED 256
#define PAIRS 15
#define MROWS 16384
#define KPAIR 512
#define KFIN  3840

#define BM 64
#define KC 32
#define NTHREADS 512
#define PITCH 80                          // A smem row: 32 fp16 = 64B + 16B pad
#define ATILE (64 * PITCH)                // 5120 B
#define PITCHB 528                        // B smem row: 256 fp16 = 512B + 16B pad
#define BTILE (KC * PITCHB)               // 16896 B   [k][n] natural layout
#define BUFB  (ATILE + BTILE)             // 22016 B
#define HPITCH 528
#define HOFF  (3 * BUFB)                  // 66048
#define SMEM_BYTES (HOFF + 64 * HPITCH)   // 99840

#define NCH1 (KPAIR / KC)                 // 16
#define NCH2 (EMBED / KC)                 // 8

// ---- fp16 weights, original [k][n] layouts (allocation-guard-safe) ----
static __device__ __half g_Wp16[(size_t)PAIRS * KPAIR * EMBED];  // [p][k][n]
static __device__ __half g_Wf16[(size_t)KFIN * EMBED];           // [k][n]

__constant__ int c_pi[PAIRS] = {0,0,0,0,0,1,1,1,1,2,2,2,3,3,4};
__constant__ int c_pj[PAIRS] = {1,2,3,4,5,2,3,4,5,3,4,5,4,5,5};

__device__ __forceinline__ bool pair_on(const int* __restrict__ NAS, int p) {
    int i = c_pi[p], j = c_pj[p];
    int ni = (i < 2) ? 1 : __ldg(&NAS[i]);
    int nj = (j < 2) ? 1 : __ldg(&NAS[j]);
    return (ni != 0) && (nj != 0);
}
__device__ __forceinline__ uint32_t smem_u32(const void* p) {
    uint32_t a;
    asm("{ .reg .u64 t; cvta.to.shared.u64 t, %1; cvt.u32.u64 %0, t; }" : "=r"(a) : "l"(p));
    return a;
}

// ---- base-target PTX primitives (sm_80 baseline; valid on plain sm_103) ----
__device__ __forceinline__ void cp16(uint32_t dst, const void* src) {
    asm volatile("cp.async.cg.shared.global [%0], [%1], 16;" :: "r"(dst), "l"(src));
}
#define CP_COMMIT()      asm volatile("cp.async.commit_group;" ::: "memory")
#define CP_WAIT(n)       asm volatile("cp.async.wait_group %0;" :: "n"(n) : "memory")
#define LDM_X4(r, addr) \
    asm volatile("ldmatrix.sync.aligned.m8n8.x4.shared.b16 {%0,%1,%2,%3}, [%4];" \
        : "=r"((r)[0]), "=r"((r)[1]), "=r"((r)[2]), "=r"((r)[3]) : "r"(addr))
#define LDM_X4T(r, addr) \
    asm volatile("ldmatrix.sync.aligned.m8n8.x4.trans.shared.b16 {%0,%1,%2,%3}, [%4];" \
        : "=r"((r)[0]), "=r"((r)[1]), "=r"((r)[2]), "=r"((r)[3]) : "r"(addr))
#define MMA(d, a, b0, b1) \
    asm volatile("mma.sync.aligned.m16n8k16.row.col.f32.f16.f16.f32 " \
        "{%0,%1,%2,%3}, {%4,%5,%6,%7}, {%8,%9}, {%0,%1,%2,%3};" \
        : "+f"((d)[0]), "+f"((d)[1]), "+f"((d)[2]), "+f"((d)[3]) \
        : "r"((a)[0]), "r"((a)[1]), "r"((a)[2]), "r"((a)[3]), "r"(b0), "r"(b1))

// ---------------------------------------------------------------------------
// Prep: elementwise fp32 -> fp16 convert, gated on active pairs/segments.
// ---------------------------------------------------------------------------
#define NP1 ((size_t)PAIRS * KPAIR * EMBED)   // 1966080
#define NP2 ((size_t)KFIN * EMBED)            //  983040
__global__ void prep_convert(const float* __restrict__ W_pair,
                             const float* __restrict__ W_final,
                             const int*   __restrict__ NAS) {
    size_t i = ((size_t)blockIdx.x * blockDim.x + threadIdx.x) * 4;
    const float* src; __half* dst; size_t o;
    if (i < NP1) {
        o = i;
        int p = (int)(o / ((size_t)KPAIR * EMBED));
        if (!pair_on(NAS, p)) return;
        src = W_pair; dst = g_Wp16;
    } else {
        o = i - NP1;
        int p = (int)(o >> 8) >> 8;   // k = o/256 ; segment = k/256
        if (!pair_on(NAS, p)) return;
        src = W_final; dst = g_Wf16;
    }
    float4 v = *reinterpret_cast<const float4*>(src + o);
    __half2 h0 = __floats2half2_rn(v.x, v.y);
    __half2 h1 = __floats2half2_rn(v.z, v.w);
    *reinterpret_cast<__half2*>(dst + o)     = h0;
    *reinterpret_cast<__half2*>(dst + o + 2) = h1;
}

// ---------------------------------------------------------------------------
// Loaders
// ---------------------------------------------------------------------------
__device__ __forceinline__ void lda_regs(float4 r[2], const float* __restrict__ s) {
    r[0] = *reinterpret_cast<const float4*>(s);
    r[1] = *reinterpret_cast<const float4*>(s + 4);
}
// A: 64 rows x 32 k fp32 -> fp16; threads 0..255 (4/row x 8 fp32).
__device__ __forceinline__ void sts_cvt(char* smem, int bufofs, uint32_t dofs,
                                        const float4 r[2]) {
    float f[8] = {r[0].x, r[0].y, r[0].z, r[0].w, r[1].x, r[1].y, r[1].z, r[1].w};
    unsigned short h[8];
    #pragma unroll
    for (int q = 0; q < 8; q++)
        h[q] = __half_as_ushort(__float2half_rn(f[q]));
    *reinterpret_cast<uint4*>(smem + bufofs + dofs) =
        make_uint4((uint32_t)h[0] | ((uint32_t)h[1] << 16), (uint32_t)h[2] | ((uint32_t)h[3] << 16),
                   (uint32_t)h[4] | ((uint32_t)h[5] << 16), (uint32_t)h[6] | ((uint32_t)h[7] << 16));
}
// B tile: [32 k][256 n] fp16, contiguous 512B rows; 16 threads/row x 32B.
__device__ __forceinline__ void cp_bk(uint32_t buf, int tid, const __half* bsrc) {
    const int row = tid >> 4, c = tid & 15;
    const uint32_t d = buf + ATILE + row * PITCHB + c * 32;
    const __half* s = bsrc + (size_t)row * EMBED + c * 16;
    cp16(d, s); cp16(d + 16, s + 8);
}

// ---------------------------------------------------------------------------
// Compute. 16 warps: warpM = wid&1 (32 rows), warpN = wid>>1 (32 of 256 cols).
// All 8 fragment loads issued up front (MLP burst), then 16 dense MMAs.
// ---------------------------------------------------------------------------
__device__ __forceinline__ void mma_burst(const uint32_t a[2][2][4],
                                          const uint32_t b[2][2][4],
                                          float acc[2][4][4]) {
    #pragma unroll
    for (int ks = 0; ks < 2; ks++)
        #pragma unroll
        for (int ntp = 0; ntp < 2; ntp++) {
            MMA(acc[0][2*ntp],   a[ks][0], b[ks][ntp][0], b[ks][ntp][1]);
            MMA(acc[1][2*ntp],   a[ks][1], b[ks][ntp][0], b[ks][ntp][1]);
            MMA(acc[0][2*ntp+1], a[ks][0], b[ks][ntp][2], b[ks][ntp][3]);
            MMA(acc[1][2*ntp+1], a[ks][1], b[ks][ntp][2], b[ks][ntp][3]);
        }
}
__device__ __forceinline__ void compute1(uint32_t buf, uint32_t laneB, int warpM, int warpN,
                                         int lid, float acc[2][4][4]) {
    const int arow = lid & 15, ka = (lid >> 4) & 1;
    const uint32_t bB = buf + ATILE + warpN * 64 + laneB;
    uint32_t a[2][2][4], b[2][2][4];
    #pragma unroll
    for (int ks = 0; ks < 2; ks++) {
        #pragma unroll
        for (int mt = 0; mt < 2; mt++)
            LDM_X4(a[ks][mt], buf + (warpM*32 + mt*16 + arow) * PITCH + ks*32 + ka*16);
        #pragma unroll
        for (int ntp = 0; ntp < 2; ntp++)
            LDM_X4T(b[ks][ntp], bB + ks * 16 * PITCHB + ntp * 32);
    }
    mma_burst(a, b, acc);
}
__device__ __forceinline__ void compute2(uint32_t buf, uint32_t laneB, uint32_t hbase, int c2,
                                         int warpM, int warpN, int lid, float acc[2][4][4]) {
    const int arow = lid & 15, ka = (lid >> 4) & 1;
    const uint32_t bB = buf + ATILE + warpN * 64 + laneB;
    uint32_t a[2][2][4], b[2][2][4];
    #pragma unroll
    for (int ks = 0; ks < 2; ks++) {
        #pragma unroll
        for (int mt = 0; mt < 2; mt++)
            LDM_X4(a[ks][mt], hbase + (warpM*32 + mt*16 + arow) * HPITCH + c2*64 + ks*32 + ka*16);
        #pragma unroll
        for (int ntp = 0; ntp < 2; ntp++)
            LDM_X4T(b[ks][ntp], bB + ks * 16 * PITCHB + ntp * 32);
    }
    mma_burst(a, b, acc);
}

// ---------------------------------------------------------------------------
// Fused kernel: per 64-row block, loop active pairs:
//   H = tanh([Fi|Fj] @ Wp + bp) (smem) ; out_acc += H @ Wft[p]
// ---------------------------------------------------------------------------
__global__ __launch_bounds__(NTHREADS, 1)
void fused_mma(const float* __restrict__ features,
               const float* __restrict__ b_pair,
               const float* __restrict__ b_final,
               const int*   __restrict__ NAS,
               float*       __restrict__ out)
{
    const int rowBase = blockIdx.x * BM;
    extern __shared__ char smem[];
    const uint32_t sb = smem_u32(smem);
    const uint32_t hbase = sb + HOFF;
    const int tid = threadIdx.x, wid = tid >> 5, lid = tid & 31;
    const int warpM = wid & 1, warpN = wid >> 1;
    const int g = lid >> 2, t = lid & 3;
    const bool aldr = (tid < 256);

    // ldmatrix.trans lane address offset within warp's B block
    const uint32_t laneB = (uint32_t)(((lid & 7) + ((lid >> 3) & 1) * 8) * PITCHB
                                      + ((lid >> 4) * 8) * 2);

    // A-loader lane mapping (threads 0..255; 4/row x 8 fp32)
    const int arow = tid & 63, aq = (tid >> 6) & 3;
    const uint32_t adofs = arow * PITCH + aq * 16;
    const size_t   arofs = (size_t)arow * EMBED + aq * 8;

    int plist[PAIRS], nact = 0;
    #pragma unroll
    for (int p = 0; p < PAIRS; p++)
        if (pair_on(NAS, p)) plist[nact++] = p;

    float acc2[2][4][4];
    #pragma unroll
    for (int i = 0; i < 2; i++)
        #pragma unroll
        for (int j = 0; j < 4; j++)
            #pragma unroll
            for (int e = 0; e < 4; e++) acc2[i][j][e] = 0.0f;

    for (int pi = 0; pi < nact; pi++) {
        const int p = plist[pi];
        const float* Fi = features + ((size_t)c_pi[p] * MROWS + rowBase) * EMBED;
        const float* Fj = features + ((size_t)c_pj[p] * MROWS + rowBase) * EMBED;
        const __half* WB = g_Wp16 + (size_t)p * KPAIR * EMBED;   // [k][n]

        float acc1[2][4][4];
        #pragma unroll
        for (int i = 0; i < 2; i++)
            #pragma unroll
            for (int j = 0; j < 4; j++)
                #pragma unroll
                for (int e = 0; e < 4; e++) acc1[i][j][e] = 0.0f;

        // ---- GEMM1: 16 chunks over K=512, triple-buffered ----
        float4 rA[2];
        if (aldr) {
            lda_regs(rA, Fi + arofs);
            sts_cvt(smem, 0, adofs, rA);
        }
        cp_bk(sb, tid, WB); CP_COMMIT();
        if (aldr) lda_regs(rA, Fi + arofs + KC);
        cp_bk(sb + BUFB, tid, WB + (size_t)KC * EMBED); CP_COMMIT();

        for (int c = 0; c < NCH1; c++) {
            if (aldr) {
                if (c + 1 < NCH1) sts_cvt(smem, ((c + 1) % 3) * BUFB, adofs, rA);
                if (c + 2 < NCH1) {
                    const int k0 = (c + 2) * KC;
                    const float* base = (k0 < EMBED) ? Fi : Fj;
                    lda_regs(rA, base + arofs + (k0 & (EMBED - 1)));
                }
            }
            if (c + 1 < NCH1) { CP_WAIT(1); } else { CP_WAIT(0); }
            __syncthreads();
            if (c + 2 < NCH1) {
                cp_bk(sb + ((c + 2) % 3) * BUFB, tid, WB + (size_t)(c + 2) * KC * EMBED);
                CP_COMMIT();
            }
            compute1(sb + (c % 3) * BUFB, laneB, warpM, warpN, lid, acc1);
        }

        // ---- H epilogue: bias + tanh -> fp16 into smem H ----
        #pragma unroll
        for (int mt = 0; mt < 2; mt++) {
            const int r0 = warpM * 32 + mt * 16 + g;
            char* hrow0 = smem + HOFF + (size_t)r0 * HPITCH;
            char* hrow1 = hrow0 + 8 * HPITCH;
            #pragma unroll
            for (int nt = 0; nt < 4; nt++) {
                const int colP = warpN * 32 + nt * 8 + 2 * t;
                const float b0 = __ldg(&b_pair[p * EMBED + colP]);
                const float b1 = __ldg(&b_pair[p * EMBED + colP + 1]);
                *reinterpret_cast<__half2*>(hrow0 + colP * 2) =
                    __floats2half2_rn(tanhf(acc1[mt][nt][0] + b0), tanhf(acc1[mt][nt][1] + b1));
                *reinterpret_cast<__half2*>(hrow1 + colP * 2) =
                    __floats2half2_rn(tanhf(acc1[mt][nt][2] + b0), tanhf(acc1[mt][nt][3] + b1));
            }
        }
        __syncthreads();   // H visible; GEMM1 buffers no longer read

        // ---- GEMM2: 8 chunks over this pair's 256-wide K segment ----
        const __half* WF = g_Wf16 + (size_t)p * EMBED * EMBED;   // rows k=p*256..
        cp_bk(sb, tid, WF); CP_COMMIT();
        cp_bk(sb + BUFB, tid, WF + (size_t)KC * EMBED); CP_COMMIT();
        for (int c = 0; c < NCH2; c++) {
            if (c + 1 < NCH2) { CP_WAIT(1); } else { CP_WAIT(0); }
            __syncthreads();
            if (c + 2 < NCH2) {
                cp_bk(sb + ((c + 2) % 3) * BUFB, tid, WF + (size_t)(c + 2) * KC * EMBED);
                CP_COMMIT();
            }
            compute2(sb + (c % 3) * BUFB, laneB, hbase, c, warpM, warpN, lid, acc2);
        }
        __syncthreads();   // buffers/H free before next pair
    }

    // ---- final epilogue: + b_final, fp32 out ----
    #pragma unroll
    for (int mt = 0; mt < 2; mt++) {
        const int r0 = rowBase + warpM * 32 + mt * 16 + g;
        #pragma unroll
        for (int nt = 0; nt < 4; nt++) {
            const int colG = warpN * 32 + nt * 8 + 2 * t;
            const float b0 = __ldg(&b_final[colG]);
            const float b1 = __ldg(&b_final[colG + 1]);
            float2 v0 = make_float2(acc2[mt][nt][0] + b0, acc2[mt][nt][1] + b1);
            float2 v1 = make_float2(acc2[mt][nt][2] + b0, acc2[mt][nt][3] + b1);
            *reinterpret_cast<float2*>(out + (size_t)r0 * EMBED + colG)       = v0;
            *reinterpret_cast<float2*>(out + (size_t)(r0 + 8) * EMBED + colG) = v1;
        }
    }
}

extern "C" void kernel_launch(void* const* d_in, const int* in_sizes, int n_in,
                              void* d_out, int out_size)
{
    const float* features = (const float*)d_in[0];
    const float* W_pair   = (const float*)d_in[1];
    const float* b_pair   = (const float*)d_in[2];
    const float* W_final  = (const float*)d_in[3];
    const float* b_final  = (const float*)d_in[4];
    const int*   NAS      = (const int*)d_in[5];
    float* out = (float*)d_out;

    cudaFuncSetAttribute(fused_mma, cudaFuncAttributeMaxDynamicSharedMemorySize, SMEM_BYTES);

    const int nvec = (int)((NP1 + NP2) / 4);                 // 737280 float4s
    prep_convert<<<nvec / 256, 256>>>(W_pair, W_final, NAS);

    fused_mma<<<dim3(MROWS/BM), NTHREADS, SMEM_BYTES>>>(features, b_pair, b_final, NAS, out);
}